// round 5
// baseline (speedup 1.0000x reference)
#include <cuda_runtime.h>
#include <cstdint>

// LIF spike recurrence over the last (time) axis.
//   u = TAU*u*(1-o_prev) + x_t;  o = (u > VTH) ? 1 : 0
// x: [16,128,512,32] fp32 -> 1,048,576 neurons x 32 contiguous timesteps.
//
// Round 5: local bit-packed spikes. cp.async double-buffered smem transpose
// on the input (coalesced reads); recurrence is pure scalar per lane with
// spikes packed into one 32-bit register (bit t = spike at step t):
//   u = s ? x_t : fma(TAU, u, x_t);  s = u > VTH;  bits |= s << t
// Store phase rebuilds coalesced float4s with ONE shfl per store (8/warp-tile)
// + bit extract * 0x3F800000 (no I2F, no ballots). Warp-autonomous.

#define TAU 0.25f
#define VTH 0.5f

#define THREADS 128
#define WARPS 4
#define F4_PER_WARP 256                    // 32 neurons * 8 float4
#define F4_PER_TILE (WARPS * F4_PER_WARP)  // 1024 float4 = 16 KB
#define FULLM 0xFFFFFFFFu

__device__ __forceinline__ void cp_async16(uint32_t smem_addr, const void* gptr) {
    asm volatile("cp.async.cg.shared.global [%0], [%1], 16;\n"
                 :: "r"(smem_addr), "l"(gptr) : "memory");
}
__device__ __forceinline__ void cp_commit() {
    asm volatile("cp.async.commit_group;\n" ::: "memory");
}
template <int N>
__device__ __forceinline__ void cp_wait() {
    asm volatile("cp.async.wait_group %0;\n" :: "n"(N) : "memory");
}

__device__ __forceinline__ float bit2f(uint32_t w, int t) {
    return __uint_as_float(((w >> t) & 1u) * 0x3F800000u);
}

__global__ __launch_bounds__(THREADS, 6)
void lif_kernel(const float4* __restrict__ x, float4* __restrict__ out,
                int ntiles) {
    __shared__ float4 buf[2][F4_PER_TILE];  // 32 KB

    const int lane = threadIdx.x & 31;
    const int warp = threadIdx.x >> 5;

    auto prefetch = [&](int tile, int b) {
        const size_t gbase = (size_t)tile * F4_PER_TILE + (size_t)warp * F4_PER_WARP;
        uint32_t sbase = (uint32_t)__cvta_generic_to_shared(
            &buf[b][warp * F4_PER_WARP]);
        #pragma unroll
        for (int i = 0; i < 8; i++) {
            int g = i * 32 + lane;
            int n = g >> 3;
            int j = g & 7;
            cp_async16(sbase + (((n << 3) | (j ^ (n & 7))) * 16u),
                       &x[gbase + g]);
        }
        cp_commit();
    };

    int tile = blockIdx.x;
    int b = 0;
    if (tile < ntiles) prefetch(tile, 0);

    for (; tile < ntiles; tile += gridDim.x) {
        const int next = tile + gridDim.x;
        if (next < ntiles) {
            prefetch(next, b ^ 1);
            cp_wait<1>();
        } else {
            cp_wait<0>();
        }
        __syncwarp();   // all lanes' cp.async data visible warp-wide

        const float4* wtile = &buf[b][warp * F4_PER_WARP];

        // Recurrence: lane owns neuron `lane`; 32 spike bits accumulate
        // locally (bit t = spike at timestep t). No cross-lane ops here.
        uint32_t bits = 0;
        {
            const int n = lane;
            float u = 0.0f;
            bool s = false;
            #pragma unroll
            for (int j = 0; j < 8; j++) {
                float4 f = wtile[(n << 3) | (j ^ (n & 7))];

                #pragma unroll
                for (int k = 0; k < 4; k++) {
                    float xv = (k == 0) ? f.x : (k == 1) ? f.y
                             : (k == 2) ? f.z : f.w;
                    u = s ? xv : fmaf(TAU, u, xv);   // reset-or-leak + input
                    s = (u > VTH);
                    bits |= (uint32_t)s << (j * 4 + k);
                }
            }
        }
        __syncwarp();   // lanes done reading buf[b] before it's re-prefetched

        // Coalesced float4 stores: one shfl per iteration pulls neuron n's
        // bit word; 4 bit-extract*0x3F800000 rebuild the fp32 spikes.
        {
            const size_t gbase = (size_t)tile * F4_PER_TILE + (size_t)warp * F4_PER_WARP;
            #pragma unroll
            for (int i = 0; i < 8; i++) {
                int g = i * 32 + lane;
                int srcl = g >> 3;            // neuron whose bits we need
                int t0 = (g & 7) * 4;         // first timestep of this float4
                uint32_t w = __shfl_sync(FULLM, bits, srcl);
                float4 v;
                v.x = bit2f(w, t0 + 0);
                v.y = bit2f(w, t0 + 1);
                v.z = bit2f(w, t0 + 2);
                v.w = bit2f(w, t0 + 3);
                __stcs(&out[gbase + g], v);
            }
        }

        b ^= 1;
    }
}

extern "C" void kernel_launch(void* const* d_in, const int* in_sizes, int n_in,
                              void* d_out, int out_size) {
    const float4* x = (const float4*)d_in[0];
    float4* o = (float4*)d_out;

    long long n_floats = in_sizes[0];                  // 33,554,432
    long long neurons = n_floats / 32;                 // 1,048,576
    int ntiles = (int)(neurons / (F4_PER_TILE / 8));   // 8192 tiles of 128 neurons

    int blocks = 6 * 148;                              // one resident wave
    if (blocks > ntiles) blocks = ntiles;

    lif_kernel<<<blocks, THREADS>>>(x, o, ntiles);
}

// round 6
// speedup vs baseline: 1.0887x; 1.0887x over previous
#include <cuda_runtime.h>
#include <cstdint>

// LIF spike recurrence over the last (time) axis.
//   u = TAU*u*(1-o_prev) + x_t;  o = (u > VTH) ? 1 : 0
// x: [16,128,512,32] fp32 -> 1,048,576 neurons x 32 contiguous timesteps.
//
// Round 6: same cp.async double-buffered, bit-packed-spike pipeline as R5;
// only the SCHEDULE changes. 888 persistent blocks gave 8192 = 888*9+200
// -> 200 blocks ran 10 tiles vs 9 (+8.5% makespan tail, DRAM idle).
// Now grid = 2048 with stride loop -> exactly 4 tiles per block, and the
// HW scheduler dynamically refills retiring blocks, self-balancing SMs.

#define TAU 0.25f
#define VTH 0.5f

#define THREADS 128
#define WARPS 4
#define F4_PER_WARP 256                    // 32 neurons * 8 float4
#define F4_PER_TILE (WARPS * F4_PER_WARP)  // 1024 float4 = 16 KB
#define FULLM 0xFFFFFFFFu

__device__ __forceinline__ void cp_async16(uint32_t smem_addr, const void* gptr) {
    asm volatile("cp.async.cg.shared.global [%0], [%1], 16;\n"
                 :: "r"(smem_addr), "l"(gptr) : "memory");
}
__device__ __forceinline__ void cp_commit() {
    asm volatile("cp.async.commit_group;\n" ::: "memory");
}
template <int N>
__device__ __forceinline__ void cp_wait() {
    asm volatile("cp.async.wait_group %0;\n" :: "n"(N) : "memory");
}

__device__ __forceinline__ float bit2f(uint32_t w, int t) {
    return __uint_as_float(((w >> t) & 1u) * 0x3F800000u);
}

__global__ __launch_bounds__(THREADS, 6)
void lif_kernel(const float4* __restrict__ x, float4* __restrict__ out,
                int ntiles) {
    __shared__ float4 buf[2][F4_PER_TILE];  // 32 KB

    const int lane = threadIdx.x & 31;
    const int warp = threadIdx.x >> 5;

    auto prefetch = [&](int tile, int b) {
        const size_t gbase = (size_t)tile * F4_PER_TILE + (size_t)warp * F4_PER_WARP;
        uint32_t sbase = (uint32_t)__cvta_generic_to_shared(
            &buf[b][warp * F4_PER_WARP]);
        #pragma unroll
        for (int i = 0; i < 8; i++) {
            int g = i * 32 + lane;
            int n = g >> 3;
            int j = g & 7;
            cp_async16(sbase + (((n << 3) | (j ^ (n & 7))) * 16u),
                       &x[gbase + g]);
        }
        cp_commit();
    };

    int tile = blockIdx.x;
    int b = 0;
    if (tile < ntiles) prefetch(tile, 0);

    for (; tile < ntiles; tile += gridDim.x) {
        const int next = tile + gridDim.x;
        if (next < ntiles) {
            prefetch(next, b ^ 1);
            cp_wait<1>();
        } else {
            cp_wait<0>();
        }
        __syncwarp();   // all lanes' cp.async data visible warp-wide

        const float4* wtile = &buf[b][warp * F4_PER_WARP];

        // Recurrence: lane owns neuron `lane`; 32 spike bits accumulate
        // locally (bit t = spike at timestep t). No cross-lane ops here.
        uint32_t bits = 0;
        {
            const int n = lane;
            float u = 0.0f;
            bool s = false;
            #pragma unroll
            for (int j = 0; j < 8; j++) {
                float4 f = wtile[(n << 3) | (j ^ (n & 7))];

                #pragma unroll
                for (int k = 0; k < 4; k++) {
                    float xv = (k == 0) ? f.x : (k == 1) ? f.y
                             : (k == 2) ? f.z : f.w;
                    u = s ? xv : fmaf(TAU, u, xv);   // reset-or-leak + input
                    s = (u > VTH);
                    bits |= (uint32_t)s << (j * 4 + k);
                }
            }
        }
        __syncwarp();   // lanes done reading buf[b] before it's re-prefetched

        // Coalesced float4 stores: one shfl per iteration pulls neuron n's
        // bit word; 4 bit-extract*0x3F800000 rebuild the fp32 spikes.
        {
            const size_t gbase = (size_t)tile * F4_PER_TILE + (size_t)warp * F4_PER_WARP;
            #pragma unroll
            for (int i = 0; i < 8; i++) {
                int g = i * 32 + lane;
                int srcl = g >> 3;            // neuron whose bits we need
                int t0 = (g & 7) * 4;         // first timestep of this float4
                uint32_t w = __shfl_sync(FULLM, bits, srcl);
                float4 v;
                v.x = bit2f(w, t0 + 0);
                v.y = bit2f(w, t0 + 1);
                v.z = bit2f(w, t0 + 2);
                v.w = bit2f(w, t0 + 3);
                __stcs(&out[gbase + g], v);
            }
        }

        b ^= 1;
    }
}

extern "C" void kernel_launch(void* const* d_in, const int* in_sizes, int n_in,
                              void* d_out, int out_size) {
    const float4* x = (const float4*)d_in[0];
    float4* o = (float4*)d_out;

    long long n_floats = in_sizes[0];                  // 33,554,432
    long long neurons = n_floats / 32;                 // 1,048,576
    int ntiles = (int)(neurons / (F4_PER_TILE / 8));   // 8192 tiles of 128 neurons

    // 2048 blocks * exactly 4 tiles each (stride loop). 888 resident at a
    // time; HW scheduler refills as blocks retire -> self-balancing, no
    // persistent-block straggler tail.
    int blocks = 2048;
    if (blocks > ntiles) blocks = ntiles;

    lif_kernel<<<blocks, THREADS>>>(x, o, ntiles);
}

// round 7
// speedup vs baseline: 1.1104x; 1.0199x over previous
#include <cuda_runtime.h>
#include <cstdint>

// LIF spike recurrence over the last (time) axis.
//   u = TAU*u*(1-o_prev) + x_t;  o = (u > VTH) ? 1 : 0
// x: [16,128,512,32] fp32 -> 1,048,576 neurons x 32 contiguous timesteps.
//
// Round 7: one tile per block, HW-scheduled pipeline. Instead of software
// double-buffering (8KB smem/warp -> only 24 warps/SM), each block handles a
// single 128-neuron tile with ONE 16KB buffer and exits. __launch_bounds__
// (128,12) -> 12 blocks/SM = 48 warps; inter-block overlap hides the cp.async
// wait (retiring blocks are refilled dynamically). Coalesced cp.async reads
// into xor-swizzled smem, per-lane serial recurrence with bit-packed spikes,
// shfl+bit-extract coalesced float4 stores.

#define TAU 0.25f
#define VTH 0.5f

#define THREADS 128
#define WARPS 4
#define F4_PER_WARP 256                    // 32 neurons * 8 float4
#define F4_PER_TILE (WARPS * F4_PER_WARP)  // 1024 float4 = 16 KB
#define FULLM 0xFFFFFFFFu

__device__ __forceinline__ void cp_async16(uint32_t smem_addr, const void* gptr) {
    asm volatile("cp.async.cg.shared.global [%0], [%1], 16;\n"
                 :: "r"(smem_addr), "l"(gptr) : "memory");
}
__device__ __forceinline__ void cp_commit() {
    asm volatile("cp.async.commit_group;\n" ::: "memory");
}
__device__ __forceinline__ void cp_wait_all() {
    asm volatile("cp.async.wait_group 0;\n" ::: "memory");
}

__device__ __forceinline__ float bit2f(uint32_t w, int t) {
    return __uint_as_float(((w >> t) & 1u) * 0x3F800000u);
}

__global__ __launch_bounds__(THREADS, 12)
void lif_kernel(const float4* __restrict__ x, float4* __restrict__ out) {
    __shared__ float4 buf[F4_PER_TILE];  // 16 KB

    const int lane = threadIdx.x & 31;
    const int warp = threadIdx.x >> 5;

    const size_t gbase = (size_t)blockIdx.x * F4_PER_TILE
                       + (size_t)warp * F4_PER_WARP;
    float4* wtile = &buf[warp * F4_PER_WARP];

    // Coalesced global -> swizzled warp-local smem via cp.async (L1 bypass).
    {
        uint32_t sbase = (uint32_t)__cvta_generic_to_shared(wtile);
        #pragma unroll
        for (int i = 0; i < 8; i++) {
            int g = i * 32 + lane;
            int n = g >> 3;
            int j = g & 7;
            cp_async16(sbase + (((n << 3) | (j ^ (n & 7))) * 16u),
                       &x[gbase + g]);
        }
        cp_commit();
    }
    cp_wait_all();
    __syncwarp();   // all lanes' cp.async data visible warp-wide

    // Recurrence: lane owns neuron `lane`; 32 spike bits accumulate locally
    // (bit t = spike at timestep t). No cross-lane ops in the serial chain.
    uint32_t bits = 0;
    {
        const int n = lane;
        float u = 0.0f;
        bool s = false;
        #pragma unroll
        for (int j = 0; j < 8; j++) {
            float4 f = wtile[(n << 3) | (j ^ (n & 7))];

            #pragma unroll
            for (int k = 0; k < 4; k++) {
                float xv = (k == 0) ? f.x : (k == 1) ? f.y
                         : (k == 2) ? f.z : f.w;
                u = s ? xv : fmaf(TAU, u, xv);   // reset-or-leak + input
                s = (u > VTH);
                bits |= (uint32_t)s << (j * 4 + k);
            }
        }
    }

    // Coalesced float4 stores: one shfl per iteration pulls neuron n's bit
    // word; 4 bit-extract * 0x3F800000 rebuild the fp32 spikes.
    #pragma unroll
    for (int i = 0; i < 8; i++) {
        int g = i * 32 + lane;
        int srcl = g >> 3;            // neuron whose bits we need
        int t0 = (g & 7) * 4;         // first timestep of this float4
        uint32_t w = __shfl_sync(FULLM, bits, srcl);
        float4 v;
        v.x = bit2f(w, t0 + 0);
        v.y = bit2f(w, t0 + 1);
        v.z = bit2f(w, t0 + 2);
        v.w = bit2f(w, t0 + 3);
        __stcs(&out[gbase + g], v);
    }
}

extern "C" void kernel_launch(void* const* d_in, const int* in_sizes, int n_in,
                              void* d_out, int out_size) {
    const float4* x = (const float4*)d_in[0];
    float4* o = (float4*)d_out;

    long long n_floats = in_sizes[0];                  // 33,554,432
    long long neurons = n_floats / 32;                 // 1,048,576
    int ntiles = (int)(neurons / (F4_PER_TILE / 8));   // 8192 tiles of 128 neurons

    lif_kernel<<<ntiles, THREADS>>>(x, o);
}